// round 3
// baseline (speedup 1.0000x reference)
#include <cuda_runtime.h>
#include <math.h>

#define Bb 256
#define Tt 256
#define Dd 64
#define Hh 512

typedef unsigned long long ull;

// Scratch (device globals: allocation-free rule).
__device__ float g_xp[(size_t)Bb * Tt * Hh];
__device__ float g_h [(size_t)Bb * Tt * Hh];
__device__ int   g_bar[3 * 16];          // per (layer, batch-group) arrival counters

// ---------------- packed dual-fp32 helpers (sm_100+ f32x2) ----------------
__device__ __forceinline__ ull fma2(ull a, ull b, ull c) {
    ull d;
    asm("fma.rn.f32x2 %0, %1, %2, %3;" : "=l"(d) : "l"(a), "l"(b), "l"(c));
    return d;
}
__device__ __forceinline__ ull dup2(float x) {
    ull d;
    asm("mov.b64 %0, {%1, %2};" : "=l"(d) : "f"(x), "f"(x));
    return d;
}
__device__ __forceinline__ float2 unpack2(ull v) {
    float2 r;
    asm("mov.b64 {%0, %1}, %2;" : "=f"(r.x), "=f"(r.y) : "l"(v));
    return r;
}

__global__ void zero_bar_kernel() {
    if (threadIdx.x < 48) g_bar[threadIdx.x] = 0;
}

// ---------------------------------------------------------------------------
// Projection GEMM: out[M,Hh] = A[M,K] @ W[K,Hh] + bias    (M = Bb*Tt)
// Tile 128x128, BK=16, 256 threads, thread tile 8x8 via f32x2.
// ---------------------------------------------------------------------------
template <int K>
__global__ __launch_bounds__(256) void proj_kernel(
    const float* __restrict__ A, const float* __restrict__ W,
    const float* __restrict__ bias, float* __restrict__ out)
{
    __shared__ float sA[16 * 132];   // transposed: sA[k*132 + m]
    __shared__ float sB[16 * 128];   // sB[k*128 + n]

    const int n0 = blockIdx.x * 128;
    const int m0 = blockIdx.y * 128;
    const int tid = threadIdx.x;
    const int tx = tid & 15;         // col group of 8
    const int ty = tid >> 4;         // row group of 8

    const int arow = tid >> 1;            // 0..127
    const int ak   = (tid & 1) * 8;       // 0 or 8
    const int bk   = tid >> 4;            // 0..15
    const int bc   = (tid & 15) * 8;      // 0..120

    ull acc[8][4];
#pragma unroll
    for (int i = 0; i < 8; i++)
#pragma unroll
        for (int j = 0; j < 4; j++) acc[i][j] = 0ull;

    // prefetch first tiles
    float4 va0 = *(const float4*)&A[(size_t)(m0 + arow) * K + ak];
    float4 va1 = *(const float4*)&A[(size_t)(m0 + arow) * K + ak + 4];
    float4 vb0 = *(const float4*)&W[(size_t)bk * Hh + n0 + bc];
    float4 vb1 = *(const float4*)&W[(size_t)bk * Hh + n0 + bc + 4];

    const int NB = K / 16;
    for (int kb = 0; kb < NB; kb++) {
        sA[(ak + 0) * 132 + arow] = va0.x;
        sA[(ak + 1) * 132 + arow] = va0.y;
        sA[(ak + 2) * 132 + arow] = va0.z;
        sA[(ak + 3) * 132 + arow] = va0.w;
        sA[(ak + 4) * 132 + arow] = va1.x;
        sA[(ak + 5) * 132 + arow] = va1.y;
        sA[(ak + 6) * 132 + arow] = va1.z;
        sA[(ak + 7) * 132 + arow] = va1.w;
        *(float4*)&sB[bk * 128 + bc]     = vb0;
        *(float4*)&sB[bk * 128 + bc + 4] = vb1;
        __syncthreads();

        if (kb + 1 < NB) {
            int k0 = (kb + 1) * 16;
            va0 = *(const float4*)&A[(size_t)(m0 + arow) * K + k0 + ak];
            va1 = *(const float4*)&A[(size_t)(m0 + arow) * K + k0 + ak + 4];
            vb0 = *(const float4*)&W[(size_t)(k0 + bk) * Hh + n0 + bc];
            vb1 = *(const float4*)&W[(size_t)(k0 + bk) * Hh + n0 + bc + 4];
        }

#pragma unroll
        for (int kk = 0; kk < 16; kk++) {
            float4 a0 = *(const float4*)&sA[kk * 132 + ty * 8];
            float4 a1 = *(const float4*)&sA[kk * 132 + ty * 8 + 4];
            ulonglong2 b0 = *(const ulonglong2*)&sB[kk * 128 + tx * 8];
            ulonglong2 b1 = *(const ulonglong2*)&sB[kk * 128 + tx * 8 + 4];
            float ar[8] = {a0.x, a0.y, a0.z, a0.w, a1.x, a1.y, a1.z, a1.w};
#pragma unroll
            for (int r = 0; r < 8; r++) {
                ull av = dup2(ar[r]);
                acc[r][0] = fma2(av, b0.x, acc[r][0]);
                acc[r][1] = fma2(av, b0.y, acc[r][1]);
                acc[r][2] = fma2(av, b1.x, acc[r][2]);
                acc[r][3] = fma2(av, b1.y, acc[r][3]);
            }
        }
        __syncthreads();
    }

    float4 bi0 = *(const float4*)&bias[n0 + tx * 8];
    float4 bi1 = *(const float4*)&bias[n0 + tx * 8 + 4];
#pragma unroll
    for (int r = 0; r < 8; r++) {
        float2 u0 = unpack2(acc[r][0]);
        float2 u1 = unpack2(acc[r][1]);
        float2 u2 = unpack2(acc[r][2]);
        float2 u3 = unpack2(acc[r][3]);
        float4 o0, o1;
        o0.x = u0.x + bi0.x; o0.y = u0.y + bi0.y; o0.z = u1.x + bi0.z; o0.w = u1.y + bi0.w;
        o1.x = u2.x + bi1.x; o1.y = u2.y + bi1.y; o1.z = u3.x + bi1.z; o1.w = u3.y + bi1.w;
        size_t base = (size_t)(m0 + ty * 8 + r) * Hh + n0 + tx * 8;
        *(float4*)&out[base]     = o0;
        *(float4*)&out[base + 4] = o1;
    }
}

// ---------------------------------------------------------------------------
// Persistent layer kernel. Grid (8 col-tiles x 16 batch-groups) = 128 CTAs,
// 256 threads. Wh slice [512x64] SMEM-resident. Per-warp staging of the
// warp's own k-chunk of h_{t-1}; release/acquire flag sync; split-k(8)
// with smem reduction reusing the staging region.
// ---------------------------------------------------------------------------
#define SH_STR  66
#define WREG    (16 * SH_STR)                // 1056 floats per warp region
#define SW_FLOATS (512 * 64)
#define AUX_FLOATS (8 * WREG)                // 8448
#define LAYER_SMEM ((SW_FLOATS + AUX_FLOATS) * 4)

extern __shared__ float s_mem[];

__device__ __forceinline__ int ld_acquire(const int* p) {
    int v;
    asm volatile("ld.acquire.gpu.global.b32 %0, [%1];" : "=r"(v) : "l"(p));
    return v;
}
__device__ __forceinline__ void red_release_add(int* p, int v) {
    asm volatile("red.release.gpu.global.add.s32 [%0], %1;" :: "l"(p), "r"(v) : "memory");
}

__global__ __launch_bounds__(256, 1) void layer_kernel(
    const float* __restrict__ xp, const float* __restrict__ Wh,
    float* __restrict__ h, int* __restrict__ bar, int layer)
{
    float* sW   = s_mem;                 // [512][64]
    float* sAux = s_mem + SW_FLOATS;     // per-warp h slice / reduction partials

    const int n0 = blockIdx.x * 64;
    const int b0 = blockIdx.y * 16;
    int* cnt = &bar[layer * 16 + blockIdx.y];

    const int tid  = threadIdx.x;
    const int w    = tid >> 5;
    const int lane = tid & 31;
    const int rg   = lane >> 3;          // 4 row groups (of 4 rows)
    const int cg   = lane & 7;           // 8 col groups
    const int kbase = w * 64;
    const int tx = tid & 15;             // epilogue col group of 4
    const int ty = tid >> 4;             // epilogue batch row

    float* sHw = &sAux[w * WREG];        // this warp's region

    // ---- stage Wh[:, n0:n0+64] once ----
    for (int i = tid; i < 512 * 16; i += 256) {
        int k = i >> 4, c4 = i & 15;
        float4 v = *(const float4*)&Wh[(size_t)k * Hh + n0 + c4 * 4];
        *(float4*)&sW[k * 64 + c4 * 4] = v;
    }

    // ---- t = 0 ----
    {
        size_t base = ((size_t)(b0 + ty) * Tt) * Hh + n0 + tx * 4;
        float4 xv = *(const float4*)&xp[base];
        float4 o;
        o.x = tanhf(xv.x); o.y = tanhf(xv.y); o.z = tanhf(xv.z); o.w = tanhf(xv.w);
        *(float4*)&h[base] = o;
        __syncthreads();                 // also covers sW staging
        if (tid == 0) red_release_add(cnt, 1);
    }

    const int srow = lane >> 4;          // staging: which of 2 rows per pass
    const int sc4  = lane & 15;          // staging: float4 within row

    for (int t = 1; t < Tt; t++) {
        // prefetch xp for this step (independent of the flag)
        size_t obase = (((size_t)(b0 + ty) * Tt) + t) * Hh + n0 + tx * 4;
        float4 xv = *(const float4*)&xp[obase];

        // ---- wait for h_{t-1} (per-warp acquire poll) ----
        if (lane == 0) {
            while (ld_acquire(cnt) < 8 * t) { }
        }
        __syncwarp();

        // ---- per-warp stage of h_{t-1}[b0..b0+15, kbase..kbase+63] ----
        float4 sv[8];
#pragma unroll
        for (int p = 0; p < 8; p++) {
            int r = p * 2 + srow;
            sv[p] = *(const float4*)&h[(((size_t)(b0 + r) * Tt) + (t - 1)) * Hh + kbase + sc4 * 4];
        }
#pragma unroll
        for (int p = 0; p < 8; p++) {
            int r = p * 2 + srow;
            float* d = &sHw[r * SH_STR + sc4 * 4];
            *(float2*)&d[0] = make_float2(sv[p].x, sv[p].y);
            *(float2*)&d[2] = make_float2(sv[p].z, sv[p].w);
        }
        __syncwarp();

        // ---- compute: 16 rows x 64 cols over this warp's 64-k chunk ----
        ull acc[4][4];
#pragma unroll
        for (int i = 0; i < 4; i++)
#pragma unroll
            for (int j = 0; j < 4; j++) acc[i][j] = 0ull;

        const float* hp = &sHw[(rg * 4) * SH_STR];
        const float* wp = &sW[kbase * 64];
#pragma unroll 4
        for (int kk = 0; kk < 64; kk++) {
            ull a0 = dup2(hp[kk]);
            ull a1 = dup2(hp[SH_STR + kk]);
            ull a2 = dup2(hp[2 * SH_STR + kk]);
            ull a3 = dup2(hp[3 * SH_STR + kk]);
            ulonglong2 wlo = *(const ulonglong2*)&wp[kk * 64 + cg * 4];
            ulonglong2 whi = *(const ulonglong2*)&wp[kk * 64 + 32 + cg * 4];
            acc[0][0] = fma2(a0, wlo.x, acc[0][0]); acc[0][1] = fma2(a0, wlo.y, acc[0][1]);
            acc[0][2] = fma2(a0, whi.x, acc[0][2]); acc[0][3] = fma2(a0, whi.y, acc[0][3]);
            acc[1][0] = fma2(a1, wlo.x, acc[1][0]); acc[1][1] = fma2(a1, wlo.y, acc[1][1]);
            acc[1][2] = fma2(a1, whi.x, acc[1][2]); acc[1][3] = fma2(a1, whi.y, acc[1][3]);
            acc[2][0] = fma2(a2, wlo.x, acc[2][0]); acc[2][1] = fma2(a2, wlo.y, acc[2][1]);
            acc[2][2] = fma2(a2, whi.x, acc[2][2]); acc[2][3] = fma2(a2, whi.y, acc[2][3]);
            acc[3][0] = fma2(a3, wlo.x, acc[3][0]); acc[3][1] = fma2(a3, wlo.y, acc[3][1]);
            acc[3][2] = fma2(a3, whi.x, acc[3][2]); acc[3][3] = fma2(a3, whi.y, acc[3][3]);
        }
        __syncwarp();   // all lanes done reading sHw before overwriting with partials

        // ---- store partials into own region ----
#pragma unroll
        for (int j = 0; j < 4; j++) {
            float* dst = &sHw[(rg * 4 + j) * SH_STR];
            *(ull*)&dst[cg * 4]          = acc[j][0];
            *(ull*)&dst[cg * 4 + 2]      = acc[j][1];
            *(ull*)&dst[32 + cg * 4]     = acc[j][2];
            *(ull*)&dst[32 + cg * 4 + 2] = acc[j][3];
        }
        __syncthreads();

        // ---- reduce 8 partials, add xp, tanh, store ----
        {
            float2 s0 = make_float2(0.f, 0.f), s1 = make_float2(0.f, 0.f);
            int rbase = ty * SH_STR + tx * 4;
#pragma unroll
            for (int w2 = 0; w2 < 8; w2++) {
                float2 u0 = unpack2(*(const ull*)&sAux[w2 * WREG + rbase]);
                float2 u1 = unpack2(*(const ull*)&sAux[w2 * WREG + rbase + 2]);
                s0.x += u0.x; s0.y += u0.y; s1.x += u1.x; s1.y += u1.y;
            }
            float4 o;
            o.x = tanhf(s0.x + xv.x); o.y = tanhf(s0.y + xv.y);
            o.z = tanhf(s1.x + xv.z); o.w = tanhf(s1.y + xv.w);
            *(float4*)&h[obase] = o;
        }
        __syncthreads();   // STG done (release ordering) + region free for next stage
        if (tid == 0 && t < Tt - 1) red_release_add(cnt, 1);
    }
}

// ---------------------------------------------------------------------------
// Final: out[b] = h[b, T-1, :] @ Wf + bf
// ---------------------------------------------------------------------------
__global__ void final_kernel(const float* __restrict__ h, const float* __restrict__ Wf,
                             const float* __restrict__ bf, float* __restrict__ out)
{
    int b = blockIdx.x;
    const float* row = h + ((size_t)b * Tt + (Tt - 1)) * Hh;
    float s = 0.f;
    for (int j = threadIdx.x; j < Hh; j += 128) s += row[j] * Wf[j];
#pragma unroll
    for (int o = 16; o > 0; o >>= 1) s += __shfl_down_sync(0xffffffffu, s, o);
    __shared__ float ws[4];
    if ((threadIdx.x & 31) == 0) ws[threadIdx.x >> 5] = s;
    __syncthreads();
    if (threadIdx.x == 0) out[b] = ws[0] + ws[1] + ws[2] + ws[3] + bf[0];
}

// ---------------------------------------------------------------------------
extern "C" void kernel_launch(void* const* d_in, const int* in_sizes, int n_in,
                              void* d_out, int out_size)
{
    const float* x   = (const float*)d_in[0];
    const float* Wx0 = (const float*)d_in[1];
    const float* Wh0 = (const float*)d_in[2];
    const float* b0  = (const float*)d_in[3];
    const float* Wx1 = (const float*)d_in[4];
    const float* Wh1 = (const float*)d_in[5];
    const float* b1  = (const float*)d_in[6];
    const float* Wx2 = (const float*)d_in[7];
    const float* Wh2 = (const float*)d_in[8];
    const float* b2  = (const float*)d_in[9];
    const float* Wf  = (const float*)d_in[10];
    const float* bf  = (const float*)d_in[11];
    float* out = (float*)d_out;

    void* p;
    cudaGetSymbolAddress(&p, g_xp);
    float* xp = (float*)p;
    cudaGetSymbolAddress(&p, g_h);
    float* hb = (float*)p;
    cudaGetSymbolAddress(&p, g_bar);
    int* bar = (int*)p;

    cudaFuncSetAttribute(layer_kernel, cudaFuncAttributeMaxDynamicSharedMemorySize, LAYER_SMEM);

    dim3 pgrid(Hh / 128, (Bb * Tt) / 128);   // (4, 512)
    dim3 lgrid(Hh / 64, Bb / 16);            // (8, 16) = 128 CTAs, all resident

    zero_bar_kernel<<<1, 64>>>();

    proj_kernel<Dd><<<pgrid, 256>>>(x, Wx0, b0, xp);
    layer_kernel<<<lgrid, 256, LAYER_SMEM>>>(xp, Wh0, hb, bar, 0);

    proj_kernel<Hh><<<pgrid, 256>>>(hb, Wx1, b1, xp);
    layer_kernel<<<lgrid, 256, LAYER_SMEM>>>(xp, Wh1, hb, bar, 1);

    proj_kernel<Hh><<<pgrid, 256>>>(hb, Wx2, b2, xp);
    layer_kernel<<<lgrid, 256, LAYER_SMEM>>>(xp, Wh2, hb, bar, 2);

    final_kernel<<<Bb, 128>>>(hb, Wf, bf, out);
}